// round 10
// baseline (speedup 1.0000x reference)
#include <cuda_runtime.h>

// SE3 graph attention, single pass, exp-without-max.
// R10: persistent grid (148*6 blocks) with atomic work-claim for perfect load
// balance / zero wave churn; edge-centric coalesced rowptr build; streaming
// output stores. Core loop (4 warps/node, float4 __ldcs, unroll 4) unchanged
// from the 82%-DRAM R9 kernel.
//
// Layouts:
//   key   : (E,8,16)  value : (E,32,4)   lane l = channel c=l
//   q     : q0 (N,32,1), q1 (N,32,3) fused -> per-lane float4
// Output: d_out[0:N*32] = feat[:,:,0]; d_out[N*32:] = feat[:,:,1:4]

#define NW   4                  // warps cooperating on one node
#define NPB  2                  // nodes per work item (block claim granularity)
#define TPB  (32 * NW * NPB)    // 256
#define MAXN 65536
#define GRID_BLOCKS (148 * 6)

__device__ int g_rowptr[MAXN + 1];
__device__ int g_counter;

// Edge-centric CSR build: thread e fills rowptr[n] = e+1 for n in (dst[e], dst[e+1]].
// Thread 0 additionally fills the head range and resets the work counter.
__global__ void rowptr_kernel(const int* __restrict__ dst, int N, int E)
{
    const int e = blockIdx.x * blockDim.x + threadIdx.x;
    if (e == 0) {
        g_counter = 0;
        const int d0 = __ldg(&dst[0]);
        for (int n = 0; n <= d0; n++) g_rowptr[n] = 0;
    }
    if (e >= E) return;
    const int d  = __ldg(&dst[e]);
    const int dn = (e + 1 < E) ? __ldg(&dst[e + 1]) : N;
    for (int n = d + 1; n <= dn; n++) g_rowptr[n] = e + 1;
}

__global__ __launch_bounds__(TPB, 6)
void se3_attn_kernel(const float* __restrict__ key,
                     const float* __restrict__ q0,
                     const float* __restrict__ q1,
                     const float* __restrict__ value,
                     float* __restrict__ out,
                     int N)
{
    const int tid = threadIdx.x;
    const int sub = tid >> 7;        // node slot within claim (0..NPB-1)
    const int t   = tid & 127;
    const int w   = t >> 5;          // warp within node group
    const int l   = t & 31;          // lane = channel c

    __shared__ int    s_base;
    __shared__ float4 sm_acc[NPB][NW][32];
    __shared__ float  sm_den[NPB][NW][32];

    const float scale = 0.08838834764831845f;   // 1/sqrt(128)

    for (;;) {
        if (tid == 0) s_base = atomicAdd(&g_counter, NPB);
        __syncthreads();
        const int base = s_base;
        if (base >= N) break;
        const int n = base + sub;

        float4 acc = make_float4(0.f, 0.f, 0.f, 0.f);
        float  den = 0.f;

        if (n < N) {
            const int e0 = g_rowptr[n];
            const int e1 = g_rowptr[n + 1];

            float4 q;
            q.x = __ldg(&q0[n * 32 + l]);
            q.y = __ldg(&q1[n * 96 + 3 * l + 0]);
            q.z = __ldg(&q1[n * 96 + 3 * l + 1]);
            q.w = __ldg(&q1[n * 96 + 3 * l + 2]);

            #pragma unroll 4
            for (int e = e0 + w; e < e1; e += NW) {
                const float4* kp = (const float4*)(key   + (size_t)e * 128) + l;
                const float4* vp = (const float4*)(value + (size_t)e * 128) + l;
                const float4 k4 = __ldcs(kp);
                const float4 v4 = __ldcs(vp);

                float part = k4.x * q.x + k4.y * q.y + k4.z * q.z + k4.w * q.w;
                part += __shfl_xor_sync(0xffffffffu, part, 2);
                part += __shfl_xor_sync(0xffffffffu, part, 1);

                const float p = __expf(part * scale);
                den   += p;
                acc.x += p * v4.x;
                acc.y += p * v4.y;
                acc.z += p * v4.z;
                acc.w += p * v4.w;
            }
        }

        sm_acc[sub][w][l] = acc;
        sm_den[sub][w][l] = den;
        __syncthreads();

        if (w == 0 && n < N) {
            #pragma unroll
            for (int i = 1; i < NW; i++) {
                const float4 a = sm_acc[sub][i][l];
                acc.x += a.x; acc.y += a.y; acc.z += a.z; acc.w += a.w;
                den += sm_den[sub][i][l];
            }
            const float inv = (den > 0.f) ? __frcp_rn(den) : 0.f;
            __stwt(&out[n * 32 + l], acc.x * inv);
            const size_t b = (size_t)N * 32 + (size_t)n * 96 + 3 * l;
            __stwt(&out[b + 0], acc.y * inv);
            __stwt(&out[b + 1], acc.z * inv);
            __stwt(&out[b + 2], acc.w * inv);
        }
        __syncthreads();   // protect s_base / smem reuse across iterations
    }
}

extern "C" void kernel_launch(void* const* d_in, const int* in_sizes, int n_in,
                              void* d_out, int out_size)
{
    const float* key   = (const float*)d_in[0];   // (E, 8, 16)
    const float* q0    = (const float*)d_in[1];   // (N, 32, 1)
    const float* q1    = (const float*)d_in[2];   // (N, 32, 3)
    const float* value = (const float*)d_in[3];   // (E, 32, 4)
    const int*   dst   = (const int*)d_in[4];     // (E,)
    float* out = (float*)d_out;

    const int E = in_sizes[4];
    const int N = in_sizes[1] / 32;

    const int rp_threads = 256;
    const int rp_blocks  = (E + rp_threads - 1) / rp_threads;
    rowptr_kernel<<<rp_blocks, rp_threads>>>(dst, N, E);

    se3_attn_kernel<<<GRID_BLOCKS, TPB>>>(key, q0, q1, value, out, N);
}

// round 14
// speedup vs baseline: 1.0496x; 1.0496x over previous
#include <cuda_runtime.h>

// SE3 graph attention, single pass, exp-without-max.
// R11: R9 static mapping (best: 103.5us kernel @ 82% DRAM) + edge-centric
// coalesced rowptr prologue + __stwt streaming output stores + unroll 8
// (per-warp trip count ~8, so one batch of 16 in-flight LDG.128 covers the
// whole node -> better DRAM latency cover).
//
// Layouts:
//   key   : (E,8,16)  value : (E,32,4)   lane l = channel c=l
//   q     : q0 (N,32,1), q1 (N,32,3) fused -> per-lane float4
// Output: d_out[0:N*32] = feat[:,:,0]; d_out[N*32:] = feat[:,:,1:4]

#define NW   4                  // warps cooperating on one node
#define NPB  2                  // nodes per block
#define TPB  (32 * NW * NPB)    // 256
#define MAXN 65536

__device__ int g_rowptr[MAXN + 1];

// Edge-centric CSR build: thread e fills rowptr[n] = e+1 for n in (dst[e], dst[e+1]].
__global__ void rowptr_kernel(const int* __restrict__ dst, int N, int E)
{
    const int e = blockIdx.x * blockDim.x + threadIdx.x;
    if (e == 0) {
        const int d0 = __ldg(&dst[0]);
        for (int n = 0; n <= d0; n++) g_rowptr[n] = 0;
    }
    if (e >= E) return;
    const int d  = __ldg(&dst[e]);
    const int dn = (e + 1 < E) ? __ldg(&dst[e + 1]) : N;
    for (int n = d + 1; n <= dn; n++) g_rowptr[n] = e + 1;
}

__global__ __launch_bounds__(TPB, 6)
void se3_attn_kernel(const float* __restrict__ key,
                     const float* __restrict__ q0,
                     const float* __restrict__ q1,
                     const float* __restrict__ value,
                     float* __restrict__ out,
                     int N)
{
    const int tid = threadIdx.x;
    const int sub = tid >> 7;        // node slot within block (0..NPB-1)
    const int t   = tid & 127;
    const int w   = t >> 5;          // warp within node group
    const int l   = t & 31;          // lane = channel c
    const int n   = blockIdx.x * NPB + sub;

    __shared__ float4 sm_acc[NPB][NW][32];
    __shared__ float  sm_den[NPB][NW][32];

    float4 acc = make_float4(0.f, 0.f, 0.f, 0.f);
    float  den = 0.f;

    if (n < N) {
        const int e0 = g_rowptr[n];
        const int e1 = g_rowptr[n + 1];

        // Per-lane query float4: q_fused[n][c=l][j=0..3]
        float4 q;
        q.x = __ldg(&q0[n * 32 + l]);
        q.y = __ldg(&q1[n * 96 + 3 * l + 0]);
        q.z = __ldg(&q1[n * 96 + 3 * l + 1]);
        q.w = __ldg(&q1[n * 96 + 3 * l + 2]);

        const float scale = 0.08838834764831845f;   // 1/sqrt(128)

        #pragma unroll 8
        for (int e = e0 + w; e < e1; e += NW) {
            const float4* kp = (const float4*)(key   + (size_t)e * 128) + l;
            const float4* vp = (const float4*)(value + (size_t)e * 128) + l;
            const float4 k4 = __ldcs(kp);
            const float4 v4 = __ldcs(vp);

            float part = k4.x * q.x + k4.y * q.y + k4.z * q.z + k4.w * q.w;
            part += __shfl_xor_sync(0xffffffffu, part, 2);
            part += __shfl_xor_sync(0xffffffffu, part, 1);

            const float p = __expf(part * scale);
            den   += p;
            acc.x += p * v4.x;
            acc.y += p * v4.y;
            acc.z += p * v4.z;
            acc.w += p * v4.w;
        }
    }

    sm_acc[sub][w][l] = acc;
    sm_den[sub][w][l] = den;
    __syncthreads();

    if (w == 0 && n < N) {
        #pragma unroll
        for (int i = 1; i < NW; i++) {
            const float4 a = sm_acc[sub][i][l];
            acc.x += a.x; acc.y += a.y; acc.z += a.z; acc.w += a.w;
            den += sm_den[sub][i][l];
        }
        const float inv = (den > 0.f) ? __frcp_rn(den) : 0.f;
        __stwt(&out[n * 32 + l], acc.x * inv);
        const size_t b = (size_t)N * 32 + (size_t)n * 96 + 3 * l;
        __stwt(&out[b + 0], acc.y * inv);
        __stwt(&out[b + 1], acc.z * inv);
        __stwt(&out[b + 2], acc.w * inv);
    }
}

extern "C" void kernel_launch(void* const* d_in, const int* in_sizes, int n_in,
                              void* d_out, int out_size)
{
    const float* key   = (const float*)d_in[0];   // (E, 8, 16)
    const float* q0    = (const float*)d_in[1];   // (N, 32, 1)
    const float* q1    = (const float*)d_in[2];   // (N, 32, 3)
    const float* value = (const float*)d_in[3];   // (E, 32, 4)
    const int*   dst   = (const int*)d_in[4];     // (E,)
    float* out = (float*)d_out;

    const int E = in_sizes[4];
    const int N = in_sizes[1] / 32;

    const int rp_threads = 256;
    const int rp_blocks  = (E + rp_threads - 1) / rp_threads;
    rowptr_kernel<<<rp_blocks, rp_threads>>>(dst, N, E);

    const int blocks = (N + NPB - 1) / NPB;
    se3_attn_kernel<<<blocks, TPB>>>(key, q0, q1, value, out, N);
}